// round 2
// baseline (speedup 1.0000x reference)
#include <cuda_runtime.h>
#include <math.h>

// Problem constants
#define DIM      64
#define NREL     16
#define NCOLS    (NREL * DIM)        // 1024
#define MAX_N    120000
#define MAX_E    1600000

// ---- scratch (device globals; no allocations allowed) ----
__device__ __align__(256) float    g_trans[(size_t)MAX_N * NCOLS];  // [n][rel*64+k]
__device__ __align__(256) float    g_att[MAX_E];
__device__ __align__(256) float    g_ex[MAX_E];
__device__ __align__(256) unsigned g_nmax[MAX_N];   // order-encoded float max
__device__ __align__(256) float    g_denom[MAX_N];

// order-preserving float<->uint encoding
__device__ __forceinline__ unsigned enc_f(float f) {
    unsigned b = __float_as_uint(f);
    return (b & 0x80000000u) ? ~b : (b | 0x80000000u);
}
__device__ __forceinline__ float dec_f(unsigned u) {
    return __uint_as_float((u & 0x80000000u) ? (u & 0x7FFFFFFFu) : ~u);
}

// packed f32x2 helpers (Blackwell FFMA2 path — not emitted by ptxas from C++)
#define FMA2(acc, a, b) \
    asm("fma.rn.f32x2 %0, %1, %2, %0;" : "+l"(acc) : "l"(a), "l"(b))
#define PACK_DUP(dst, s) \
    asm("mov.b64 %0, {%1, %1};" : "=l"(dst) : "f"(s))
#define UNPACK2(lo, hi, p) \
    asm("mov.b64 {%0, %1}, %2;" : "=f"(lo), "=f"(hi) : "l"(p))

// ---- K0: init per-node accumulators ----
__global__ void init_kernel(int n) {
    int i = blockIdx.x * blockDim.x + threadIdx.x;
    if (i < n) { g_nmax[i] = 0u; g_denom[i] = 0.0f; }
}

// ---- K1: trans[m][r*64+k] = sum_d emb[m][d] * W[r][d][k], packed-f32x2 FFMA ----
// CTA tile 128 rows x 64 cols, one relation per blockIdx.y. 256 threads.
// A staged TRANSPOSED in smem ([d][row], XOR-swizzled) so row-pairs load as LDS.64.
// Per-thread microtile: 8 rows x 4 cols = 4x4 packed f32x2 accumulators.
__global__ __launch_bounds__(256) void gemm_kernel(
    const float* __restrict__ emb, const float* __restrict__ W, int M)
{
    __shared__ __align__(16) float As_t[64 * 128];  // 32 KB, [d][row^swz]
    __shared__ __align__(16) float Bs[64 * 64];     // 16 KB, [d][k]

    const int tid  = threadIdx.x;
    const int m0   = blockIdx.x * 128;
    const int rrel = blockIdx.y;
    const float* Wr = W + (size_t)rrel * (DIM * DIM);

    // load A tile transposed: thread (c4, r) handles float4 column c4 of rows r+16p
    {
        int c4 = tid & 15;   // source float4 column => d = 4*c4+q
        int r  = tid >> 4;   // 0..15
        #pragma unroll
        for (int p = 0; p < 8; p++) {
            int row = r + p * 16;
            int gm  = m0 + row;
            float4 v = (gm < M)
                ? ((const float4*)(emb + (size_t)gm * DIM))[c4]
                : make_float4(0.f, 0.f, 0.f, 0.f);
            int d0 = c4 * 4;
            // swizzle: store at row ^ (2*(d&15)); even XOR keeps (row,row+1) pairs adjacent
            As_t[(d0 + 0) * 128 + (row ^ ((( d0 + 0) & 15) * 2))] = v.x;
            As_t[(d0 + 1) * 128 + (row ^ ((( d0 + 1) & 15) * 2))] = v.y;
            As_t[(d0 + 2) * 128 + (row ^ ((( d0 + 2) & 15) * 2))] = v.z;
            As_t[(d0 + 3) * 128 + (row ^ ((( d0 + 3) & 15) * 2))] = v.w;
        }
    }
    // load B tile (64x64), same layout as W[r]
    #pragma unroll
    for (int p = 0; p < 4; p++) {
        ((float4*)Bs)[tid + p * 256] = ((const float4*)Wr)[tid + p * 256];
    }
    __syncthreads();

    const int trow = (tid >> 4) * 8;  // 0..120
    const int tcol = (tid & 15) * 4;  // 0..60

    unsigned long long acc[4][4];
    #pragma unroll
    for (int p = 0; p < 4; p++)
        #pragma unroll
        for (int j = 0; j < 4; j++) acc[p][j] = 0ull;

    #pragma unroll 8
    for (int d = 0; d < DIM; d++) {
        const int xr = (d & 15) * 2;
        const float* arow = &As_t[d * 128];

        unsigned long long a0 = *(const unsigned long long*)&arow[(trow + 0) ^ xr];
        unsigned long long a1 = *(const unsigned long long*)&arow[(trow + 2) ^ xr];
        unsigned long long a2 = *(const unsigned long long*)&arow[(trow + 4) ^ xr];
        unsigned long long a3 = *(const unsigned long long*)&arow[(trow + 6) ^ xr];

        float4 bv = *(const float4*)&Bs[d * DIM + tcol];
        unsigned long long pb0, pb1, pb2, pb3;
        PACK_DUP(pb0, bv.x); PACK_DUP(pb1, bv.y);
        PACK_DUP(pb2, bv.z); PACK_DUP(pb3, bv.w);

        FMA2(acc[0][0], a0, pb0); FMA2(acc[0][1], a0, pb1);
        FMA2(acc[0][2], a0, pb2); FMA2(acc[0][3], a0, pb3);
        FMA2(acc[1][0], a1, pb0); FMA2(acc[1][1], a1, pb1);
        FMA2(acc[1][2], a1, pb2); FMA2(acc[1][3], a1, pb3);
        FMA2(acc[2][0], a2, pb0); FMA2(acc[2][1], a2, pb1);
        FMA2(acc[2][2], a2, pb2); FMA2(acc[2][3], a2, pb3);
        FMA2(acc[3][0], a3, pb0); FMA2(acc[3][1], a3, pb1);
        FMA2(acc[3][2], a3, pb2); FMA2(acc[3][3], a3, pb3);
    }

    // epilogue: unpack pairs (rows trow+2p, trow+2p+1), write float4 per row
    #pragma unroll
    for (int p = 0; p < 4; p++) {
        float lo0, hi0, lo1, hi1, lo2, hi2, lo3, hi3;
        UNPACK2(lo0, hi0, acc[p][0]);
        UNPACK2(lo1, hi1, acc[p][1]);
        UNPACK2(lo2, hi2, acc[p][2]);
        UNPACK2(lo3, hi3, acc[p][3]);
        int gm0 = m0 + trow + 2 * p;
        if (gm0 < M) {
            *(float4*)&g_trans[(size_t)gm0 * NCOLS + rrel * DIM + tcol] =
                make_float4(lo0, lo1, lo2, lo3);
        }
        if (gm0 + 1 < M) {
            *(float4*)&g_trans[(size_t)(gm0 + 1) * NCOLS + rrel * DIM + tcol] =
                make_float4(hi0, hi1, hi2, hi3);
        }
    }
}

// ---- K2: per-edge attention logit + segment max (warp per edge) ----
__global__ __launch_bounds__(256) void att_kernel(
    const int* __restrict__ src, const int* __restrict__ dst,
    const int* __restrict__ typ, const float* __restrict__ rel, int E)
{
    int gw   = (blockIdx.x * blockDim.x + threadIdx.x) >> 5;
    int lane = threadIdx.x & 31;
    if (gw >= E) return;

    int s = src[gw], d = dst[gw], r = typ[gw];
    const float2* t  = (const float2*)(g_trans + (size_t)s * NCOLS + r * DIM);
    const float2* h  = (const float2*)(g_trans + (size_t)d * NCOLS + r * DIM);
    const float2* re = (const float2*)(rel + (size_t)r * DIM);

    float2 tv = t[lane], hv = h[lane], rv = re[lane];
    float p = tv.x * tanhf(hv.x + rv.x) + tv.y * tanhf(hv.y + rv.y);

    #pragma unroll
    for (int o = 16; o > 0; o >>= 1) p += __shfl_xor_sync(0xffffffffu, p, o);

    if (lane == 0) {
        g_att[gw] = p;
        atomicMax(&g_nmax[d], enc_f(p));
    }
}

// ---- K3: ex = exp(att - max[dst]); segment sum ----
__global__ void exp_kernel(const int* __restrict__ dst, int E) {
    int i = blockIdx.x * blockDim.x + threadIdx.x;
    if (i < E) {
        int d  = dst[i];
        float m = dec_f(g_nmax[d]);
        float e = expf(g_att[i] - m);
        g_ex[i] = e;
        atomicAdd(&g_denom[d], e);
    }
}

// ---- K4: normalize ----
__global__ void norm_kernel(const int* __restrict__ dst, float* __restrict__ out, int E) {
    int i = blockIdx.x * blockDim.x + threadIdx.x;
    if (i < E) out[i] = g_ex[i] / g_denom[dst[i]];
}

extern "C" void kernel_launch(void* const* d_in, const int* in_sizes, int n_in,
                              void* d_out, int out_size)
{
    const float* emb = (const float*)d_in[0];  // [N, 64]
    const float* rel = (const float*)d_in[1];  // [16, 64]
    const float* W   = (const float*)d_in[2];  // [16, 64, 64]
    const int*   src = (const int*)d_in[3];    // [E]
    const int*   dst = (const int*)d_in[4];    // [E]
    const int*   typ = (const int*)d_in[5];    // [E]
    float*       out = (float*)d_out;          // [E, 1]

    int M = in_sizes[0] / DIM;
    int E = in_sizes[3];

    init_kernel<<<(M + 255) / 256, 256>>>(M);
    gemm_kernel<<<dim3((M + 127) / 128, NREL), 256>>>(emb, W, M);
    att_kernel<<<(E + 7) / 8, 256>>>(src, dst, typ, rel, E);
    exp_kernel<<<(E + 255) / 256, 256>>>(dst, E);
    norm_kernel<<<(E + 255) / 256, 256>>>(dst, out, E);
}

// round 4
// speedup vs baseline: 1.1989x; 1.1989x over previous
#include <cuda_runtime.h>
#include <cuda_bf16.h>
#include <cstdint>
#include <math.h>

#define DIM      64
#define NREL     16
#define NCOLS    (NREL * DIM)        // 1024
#define MAX_N    120000
#define MAX_E    1600000

// ---- scratch ----
__device__ __align__(256) float    g_trans[(size_t)MAX_N * NCOLS];
__device__ __align__(256) float    g_att[MAX_E];
__device__ __align__(256) float    g_ex[MAX_E];
__device__ __align__(256) unsigned g_nmax[MAX_N];
__device__ __align__(256) float    g_denom[MAX_N];

__device__ __forceinline__ unsigned enc_f(float f) {
    unsigned b = __float_as_uint(f);
    return (b & 0x80000000u) ? ~b : (b | 0x80000000u);
}
__device__ __forceinline__ float dec_f(unsigned u) {
    return __uint_as_float((u & 0x80000000u) ? (u & 0x7FFFFFFFu) : ~u);
}

__device__ __forceinline__ uint32_t smem_u32(const void* p) {
    uint32_t a;
    asm("{ .reg .u64 t; cvta.to.shared.u64 t, %1; cvt.u32.u64 %0, t; }"
        : "=r"(a) : "l"(p));
    return a;
}

// ---- warp-mma helpers (family-common PTX; legal on plain sm_103) ----
__device__ __forceinline__ void ldsm_x4(uint32_t addr, uint32_t* r) {
    asm volatile("ldmatrix.sync.aligned.m8n8.x4.shared.b16 {%0,%1,%2,%3}, [%4];"
        : "=r"(r[0]), "=r"(r[1]), "=r"(r[2]), "=r"(r[3]) : "r"(addr));
}
__device__ __forceinline__ void ldsm_x4_t(uint32_t addr, uint32_t* r) {
    asm volatile("ldmatrix.sync.aligned.m8n8.x4.trans.shared.b16 {%0,%1,%2,%3}, [%4];"
        : "=r"(r[0]), "=r"(r[1]), "=r"(r[2]), "=r"(r[3]) : "r"(addr));
}
__device__ __forceinline__ void mma_bf16(float* c, const uint32_t* a,
                                         uint32_t b0, uint32_t b1) {
    asm volatile(
        "mma.sync.aligned.m16n8k16.row.col.f32.bf16.bf16.f32 "
        "{%0,%1,%2,%3}, {%4,%5,%6,%7}, {%8,%9}, {%0,%1,%2,%3};"
        : "+f"(c[0]), "+f"(c[1]), "+f"(c[2]), "+f"(c[3])
        : "r"(a[0]), "r"(a[1]), "r"(a[2]), "r"(a[3]), "r"(b0), "r"(b1));
}

// smem layout (bytes, dynamic): bf16 tiles, 128B rows, XOR-16B swizzle by (row&7)
#define SM_AH   0
#define SM_AL   (SM_AH + 128 * 128)   // 16 KB each
#define SM_BH   (SM_AL + 128 * 128)
#define SM_BL   (SM_BH + 64 * 128)    // 8 KB each
#define SM_TOT  (SM_BL + 64 * 128)    // 49152 B

#define SWZ(row, colb) (((uint32_t)(row)) * 128u + (((uint32_t)(colb)) ^ ((((uint32_t)(row)) & 7u) << 4)))

// ---- K0 ----
__global__ void init_kernel(int n) {
    int i = blockIdx.x * blockDim.x + threadIdx.x;
    if (i < n) { g_nmax[i] = 0u; g_denom[i] = 0.0f; }
}

// ---- K1: split-bf16 warp-MMA GEMM. CTA = 128 rows x 1 relation (N=64, K=64) ----
__global__ __launch_bounds__(256, 4)
void gemm_kernel(const float* __restrict__ emb, const float* __restrict__ W, int M)
{
    extern __shared__ char smem[];
    const uint32_t sb = smem_u32(smem);
    const int tid  = threadIdx.x;
    const int wid  = tid >> 5;
    const int lane = tid & 31;
    const int m0   = blockIdx.x * 128;
    const int rrel = blockIdx.y;
    const float* Wr = W + (size_t)rrel * (DIM * DIM);

    // --- stage A (128x64 fp32 -> bf16 hi/lo) ---
    #pragma unroll
    for (int p = 0; p < 8; p++) {
        int idx = tid + p * 256;          // 0..2047
        int row = idx >> 4;
        int c4  = idx & 15;
        int gm  = m0 + row;
        float4 v = (gm < M) ? ((const float4*)(emb + (size_t)gm * DIM))[c4]
                            : make_float4(0.f, 0.f, 0.f, 0.f);
        __nv_bfloat162 h01 = make_bfloat162(__float2bfloat16(v.x), __float2bfloat16(v.y));
        __nv_bfloat162 h23 = make_bfloat162(__float2bfloat16(v.z), __float2bfloat16(v.w));
        __nv_bfloat162 l01 = make_bfloat162(
            __float2bfloat16(v.x - __bfloat162float(h01.x)),
            __float2bfloat16(v.y - __bfloat162float(h01.y)));
        __nv_bfloat162 l23 = make_bfloat162(
            __float2bfloat16(v.z - __bfloat162float(h23.x)),
            __float2bfloat16(v.w - __bfloat162float(h23.y)));
        uint32_t off = SWZ(row, c4 * 8);
        *(uint2*)(smem + SM_AH + off) =
            make_uint2(*(uint32_t*)&h01, *(uint32_t*)&h23);
        *(uint2*)(smem + SM_AL + off) =
            make_uint2(*(uint32_t*)&l01, *(uint32_t*)&l23);
    }
    // --- stage B = W_r (already [k=d][n] row-major) as bf16 hi/lo ---
    #pragma unroll
    for (int p = 0; p < 4; p++) {
        int idx = tid + p * 256;          // 0..1023 float4s
        int d  = idx >> 4;
        int c4 = idx & 15;
        float4 v = ((const float4*)Wr)[idx];
        __nv_bfloat162 h01 = make_bfloat162(__float2bfloat16(v.x), __float2bfloat16(v.y));
        __nv_bfloat162 h23 = make_bfloat162(__float2bfloat16(v.z), __float2bfloat16(v.w));
        __nv_bfloat162 l01 = make_bfloat162(
            __float2bfloat16(v.x - __bfloat162float(h01.x)),
            __float2bfloat16(v.y - __bfloat162float(h01.y)));
        __nv_bfloat162 l23 = make_bfloat162(
            __float2bfloat16(v.z - __bfloat162float(h23.x)),
            __float2bfloat16(v.w - __bfloat162float(h23.y)));
        uint32_t off = SWZ(d, c4 * 8);
        *(uint2*)(smem + SM_BH + off) =
            make_uint2(*(uint32_t*)&h01, *(uint32_t*)&h23);
        *(uint2*)(smem + SM_BL + off) =
            make_uint2(*(uint32_t*)&l01, *(uint32_t*)&l23);
    }
    __syncthreads();

    const int wr = wid * 16;              // warp's row strip within tile
    float c[8][4];
    #pragma unroll
    for (int t = 0; t < 8; t++)
        #pragma unroll
        for (int j = 0; j < 4; j++) c[t][j] = 0.0f;

    // precomputed per-lane ldmatrix address components
    const int a_midx = lane >> 3, a_r = lane & 7;
    const int a_row  = wr + (a_midx & 1) * 8 + a_r;
    const int a_colb0 = (a_midx >> 1) * 16;
    const int b_i    = lane & 7, b_half = lane >> 3;
    const int b_krow0 = (b_half & 1) * 8 + b_i;
    const int b_ncol0 = (b_half >> 1) * 16;   // bytes: +8 cols = 16B

    // three chains: (A_hi,B_hi), (A_hi,B_lo), (A_lo,B_hi)
    const uint32_t abase[3] = { sb + SM_AH, sb + SM_AH, sb + SM_AL };
    const uint32_t bbase[3] = { sb + SM_BH, sb + SM_BL, sb + SM_BH };

    #pragma unroll
    for (int ch = 0; ch < 3; ch++) {
        #pragma unroll
        for (int ks = 0; ks < 4; ks++) {
            uint32_t a[4];
            ldsm_x4(abase[ch] + SWZ(a_row, ks * 32 + a_colb0), a);
            #pragma unroll
            for (int np = 0; np < 4; np++) {
                uint32_t b[4];
                int krow = ks * 16 + b_krow0;
                ldsm_x4_t(bbase[ch] + SWZ(krow, np * 32 + b_ncol0), b);
                mma_bf16(c[np * 2 + 0], a, b[0], b[1]);
                mma_bf16(c[np * 2 + 1], a, b[2], b[3]);
            }
        }
    }

    // --- epilogue: write fragments to g_trans ---
    {
        int r0 = m0 + wr + (lane >> 2);
        int r1 = r0 + 8;
        int cb = rrel * DIM + (lane & 3) * 2;
        #pragma unroll
        for (int t = 0; t < 8; t++) {
            if (r0 < M)
                *(float2*)&g_trans[(size_t)r0 * NCOLS + cb + t * 8] =
                    make_float2(c[t][0], c[t][1]);
            if (r1 < M)
                *(float2*)&g_trans[(size_t)r1 * NCOLS + cb + t * 8] =
                    make_float2(c[t][2], c[t][3]);
        }
    }
}

// ---- K2: per-edge attention logit + segment max (warp per edge) ----
__global__ __launch_bounds__(256) void att_kernel(
    const int* __restrict__ src, const int* __restrict__ dst,
    const int* __restrict__ typ, const float* __restrict__ rel, int E)
{
    int gw   = (blockIdx.x * blockDim.x + threadIdx.x) >> 5;
    int lane = threadIdx.x & 31;
    if (gw >= E) return;

    int s = src[gw], d = dst[gw], r = typ[gw];
    const float2* t  = (const float2*)(g_trans + (size_t)s * NCOLS + r * DIM);
    const float2* h  = (const float2*)(g_trans + (size_t)d * NCOLS + r * DIM);
    const float2* re = (const float2*)(rel + (size_t)r * DIM);

    float2 tv = t[lane], hv = h[lane], rv = re[lane];
    float p = tv.x * tanhf(hv.x + rv.x) + tv.y * tanhf(hv.y + rv.y);

    #pragma unroll
    for (int o = 16; o > 0; o >>= 1) p += __shfl_xor_sync(0xffffffffu, p, o);

    if (lane == 0) {
        g_att[gw] = p;
        atomicMax(&g_nmax[d], enc_f(p));
    }
}

// ---- K3 ----
__global__ void exp_kernel(const int* __restrict__ dst, int E) {
    int i = blockIdx.x * blockDim.x + threadIdx.x;
    if (i < E) {
        int d  = dst[i];
        float m = dec_f(g_nmax[d]);
        float e = expf(g_att[i] - m);
        g_ex[i] = e;
        atomicAdd(&g_denom[d], e);
    }
}

// ---- K4 ----
__global__ void norm_kernel(const int* __restrict__ dst, float* __restrict__ out, int E) {
    int i = blockIdx.x * blockDim.x + threadIdx.x;
    if (i < E) out[i] = g_ex[i] / g_denom[dst[i]];
}

extern "C" void kernel_launch(void* const* d_in, const int* in_sizes, int n_in,
                              void* d_out, int out_size)
{
    const float* emb = (const float*)d_in[0];
    const float* rel = (const float*)d_in[1];
    const float* W   = (const float*)d_in[2];
    const int*   src = (const int*)d_in[3];
    const int*   dst = (const int*)d_in[4];
    const int*   typ = (const int*)d_in[5];
    float*       out = (float*)d_out;

    int M = in_sizes[0] / DIM;
    int E = in_sizes[3];

    static bool attr_set = false;
    if (!attr_set) {
        cudaFuncSetAttribute(gemm_kernel,
                             cudaFuncAttributeMaxDynamicSharedMemorySize, SM_TOT);
        attr_set = true;
    }

    init_kernel<<<(M + 255) / 256, 256>>>(M);
    gemm_kernel<<<dim3((M + 127) / 128, NREL), 256, SM_TOT>>>(emb, W, M);
    att_kernel<<<(E + 7) / 8, 256>>>(src, dst, typ, rel, E);
    exp_kernel<<<(E + 255) / 256, 256>>>(dst, E);
    norm_kernel<<<(E + 255) / 256, 256>>>(dst, out, E);
}